// round 1
// baseline (speedup 1.0000x reference)
#include <cuda_runtime.h>
#include <math.h>

#define BB 2
#define CC 3
#define HF 1080
#define WF 1920
#define HH 540
#define WH 960

// Scratch (static device globals — no allocations allowed)
__device__ float  g_luma [BB*HH*WH];   // half-res luma
__device__ float  g_edge [BB*HH*WH];   // edge magnitude (pre/post blur)
__device__ float  g_tmp  [BB*HH*WH];   // blur intermediate
__device__ float2 g_gradh[BB*HH*WH];   // half-res gradient field (x,y)
__device__ float2 g_gradf[BB*HF*WF];   // full-res gradient field (x,y)

// Bilinear sample with border clamp, align_corners pixel coords already applied
__device__ __forceinline__ float bsample(const float* __restrict__ p,
                                         float y, float x, int H, int W) {
    y = fminf(fmaxf(y, 0.f), (float)(H - 1));
    x = fminf(fmaxf(x, 0.f), (float)(W - 1));
    int y0 = (int)floorf(y), x0 = (int)floorf(x);
    int y1 = min(y0 + 1, H - 1), x1 = min(x0 + 1, W - 1);
    float wy = y - (float)y0, wx = x - (float)x0;
    float v00 = p[y0 * W + x0], v01 = p[y0 * W + x1];
    float v10 = p[y1 * W + x0], v11 = p[y1 * W + x1];
    return (v00 * (1.f - wx) + v01 * wx) * (1.f - wy)
         + (v10 * (1.f - wx) + v11 * wx) * wy;
}

// ---------------------------------------------------------------------------
// Kernel 1: luma + bilinear downsample to 540x960 (align_corners)
// ---------------------------------------------------------------------------
__global__ void k_luma_down(const float* __restrict__ img) {
    int j = blockIdx.x * blockDim.x + threadIdx.x;
    int i = blockIdx.y;
    int b = blockIdx.z;
    if (j >= WH) return;

    float y = (float)i * ((float)(HF - 1) / (float)(HH - 1));
    float x = (float)j * ((float)(WF - 1) / (float)(WH - 1));
    y = fminf(fmaxf(y, 0.f), (float)(HF - 1));
    x = fminf(fmaxf(x, 0.f), (float)(WF - 1));
    int y0 = (int)floorf(y), x0 = (int)floorf(x);
    int y1 = min(y0 + 1, HF - 1), x1 = min(x0 + 1, WF - 1);
    float wy = y - (float)y0, wx = x - (float)x0;

    const float* r = img + (size_t)b * CC * HF * WF;
    const float* g = r + (size_t)HF * WF;
    const float* bl = g + (size_t)HF * WF;

    #define LUMA(yy, xx) (0.299f * r[(yy) * WF + (xx)] + 0.587f * g[(yy) * WF + (xx)] + 0.114f * bl[(yy) * WF + (xx)])
    float v00 = LUMA(y0, x0), v01 = LUMA(y0, x1);
    float v10 = LUMA(y1, x0), v11 = LUMA(y1, x1);
    #undef LUMA

    float v = (v00 * (1.f - wx) + v01 * wx) * (1.f - wy)
            + (v10 * (1.f - wx) + v11 * wx) * wy;
    g_luma[((size_t)b * HH + i) * WH + j] = v;
}

// ---------------------------------------------------------------------------
// Kernel 2: fused sobel_x(offset=1) + sobel_y(offset=1, magnitude=True)
//   shift-sample composition = 8 bilinear taps of luma
// ---------------------------------------------------------------------------
__global__ void k_edge_mag() {
    int j = blockIdx.x * blockDim.x + threadIdx.x;
    int i = blockIdx.y;
    int b = blockIdx.z;
    if (j >= WH) return;

    const float* L = g_luma + (size_t)b * HH * WH;
    const float sx = (float)(WH - 1) / (float)WH;  // offset=1 pixel shift
    const float sy = (float)(HH - 1) / (float)HH;
    float fi = (float)i, fj = (float)j;
    float xm = fj - sx, xp = fj + sx;
    float ym = fi - sy, yp = fi + sy;

    float a_mm = bsample(L, ym, xm, HH, WH);
    float a_mc = bsample(L, ym, fj, HH, WH);
    float a_mp = bsample(L, ym, xp, HH, WH);
    float a_cm = bsample(L, fi, xm, HH, WH);
    float a_cp = bsample(L, fi, xp, HH, WH);
    float a_pm = bsample(L, yp, xm, HH, WH);
    float a_pc = bsample(L, yp, fj, HH, WH);
    float a_pp = bsample(L, yp, xp, HH, WH);

    float top0 = -a_mm + a_mp;
    float c0   = -a_cm + a_cp;
    float bot0 = -a_pm + a_pp;
    float top1 = a_mm + 2.f * a_mc + a_mp;
    float bot1 = a_pm + 2.f * a_pc + a_pp;

    float xg = (top0 + 2.f * c0 + bot0) * 0.125f;
    float yg = (bot1 - top1) * 0.125f;
    float mag = sqrtf(xg * xg + yg * yg);
    g_edge[((size_t)b * HH + i) * WH + j] = powf(mag, 0.7f);
}

// ---------------------------------------------------------------------------
// Kernel 3a/3b: 5-tap gaussian blur (sigma=1), replicate padding, separable
// ---------------------------------------------------------------------------
__constant__ float c_gw[3] = {0.40261995f, 0.24420135f, 0.05448868f};

__global__ void k_blur_h() {
    int j = blockIdx.x * blockDim.x + threadIdx.x;
    int i = blockIdx.y;
    int b = blockIdx.z;
    if (j >= WH) return;
    const float* p = g_edge + (size_t)b * HH * WH + (size_t)i * WH;
    float s = c_gw[0] * p[j];
    #pragma unroll
    for (int t = 1; t <= 2; ++t) {
        s += c_gw[t] * (p[max(j - t, 0)] + p[min(j + t, WH - 1)]);
    }
    g_tmp[((size_t)b * HH + i) * WH + j] = s;
}

__global__ void k_blur_v() {
    int j = blockIdx.x * blockDim.x + threadIdx.x;
    int i = blockIdx.y;
    int b = blockIdx.z;
    if (j >= WH) return;
    const float* p = g_tmp + (size_t)b * HH * WH;
    float s = c_gw[0] * p[(size_t)i * WH + j];
    #pragma unroll
    for (int t = 1; t <= 2; ++t) {
        s += c_gw[t] * (p[(size_t)max(i - t, 0) * WH + j] + p[(size_t)min(i + t, HH - 1) * WH + j]);
    }
    g_edge[((size_t)b * HH + i) * WH + j] = s;
}

// ---------------------------------------------------------------------------
// Kernel 4: fused sobel_x(offset=0.5) + sobel_y(offset=0.5, magnitude=False)
//   -> 2-channel gradient field at half res (interleaved float2)
// ---------------------------------------------------------------------------
__global__ void k_grad_field() {
    int j = blockIdx.x * blockDim.x + threadIdx.x;
    int i = blockIdx.y;
    int b = blockIdx.z;
    if (j >= WH) return;

    const float* E = g_edge + (size_t)b * HH * WH;
    const float sx = 0.5f * (float)(WH - 1) / (float)WH;
    const float sy = 0.5f * (float)(HH - 1) / (float)HH;
    float fi = (float)i, fj = (float)j;
    float xm = fj - sx, xp = fj + sx;
    float ym = fi - sy, yp = fi + sy;

    float a_mm = bsample(E, ym, xm, HH, WH);
    float a_mc = bsample(E, ym, fj, HH, WH);
    float a_mp = bsample(E, ym, xp, HH, WH);
    float a_cm = bsample(E, fi, xm, HH, WH);
    float a_cp = bsample(E, fi, xp, HH, WH);
    float a_pm = bsample(E, yp, xm, HH, WH);
    float a_pc = bsample(E, yp, fj, HH, WH);
    float a_pp = bsample(E, yp, xp, HH, WH);

    float top0 = -a_mm + a_mp;
    float c0   = -a_cm + a_cp;
    float bot0 = -a_pm + a_pp;
    float top1 = a_mm + 2.f * a_mc + a_mp;
    float bot1 = a_pm + 2.f * a_pc + a_pp;

    float2 gv;
    gv.x = (top0 + 2.f * c0 + bot0) * 0.125f;
    gv.y = (bot1 - top1) * 0.125f;
    g_gradh[((size_t)b * HH + i) * WH + j] = gv;
}

// ---------------------------------------------------------------------------
// Kernel 5: bilinear upsample gradient field to full res (align_corners)
// ---------------------------------------------------------------------------
__global__ void k_upsample() {
    int j = blockIdx.x * blockDim.x + threadIdx.x;
    int i = blockIdx.y;
    int b = blockIdx.z;
    if (j >= WF) return;

    float y = (float)i * ((float)(HH - 1) / (float)(HF - 1));
    float x = (float)j * ((float)(WH - 1) / (float)(WF - 1));
    y = fminf(fmaxf(y, 0.f), (float)(HH - 1));
    x = fminf(fmaxf(x, 0.f), (float)(WH - 1));
    int y0 = (int)floorf(y), x0 = (int)floorf(x);
    int y1 = min(y0 + 1, HH - 1), x1 = min(x0 + 1, WH - 1);
    float wy = y - (float)y0, wx = x - (float)x0;

    const float2* G = g_gradh + (size_t)b * HH * WH;
    float2 v00 = G[y0 * WH + x0], v01 = G[y0 * WH + x1];
    float2 v10 = G[y1 * WH + x0], v11 = G[y1 * WH + x1];

    float2 v;
    v.x = (v00.x * (1.f - wx) + v01.x * wx) * (1.f - wy)
        + (v10.x * (1.f - wx) + v11.x * wx) * wy;
    v.y = (v00.y * (1.f - wx) + v01.y * wx) * (1.f - wy)
        + (v10.y * (1.f - wx) + v11.y * wx) * wy;
    g_gradf[((size_t)b * HF + i) * WF + j] = v;
}

// ---------------------------------------------------------------------------
// Kernel 6: 6-iteration warp + final image sample + clip
// ---------------------------------------------------------------------------
__global__ void k_warp(const float* __restrict__ img, float* __restrict__ out) {
    int j = blockIdx.x * blockDim.x + threadIdx.x;
    int i = blockIdx.y;
    int b = blockIdx.z;
    if (j >= WF) return;

    float gx = 2.f * (float)j / (float)(WF - 1) - 1.f;
    float gy = 2.f * (float)i / (float)(HF - 1) - 1.f;

    const float2* G = g_gradf + (size_t)b * HF * WF;
    const float stepx = 2.f / (float)WF * 0.1f;  // relstr = 0.1
    const float stepy = 2.f / (float)HF * 0.1f;

    #pragma unroll
    for (int it = 0; it < 6; ++it) {
        float px = fminf(fmaxf((gx + 1.f) * 0.5f * (float)(WF - 1), 0.f), (float)(WF - 1));
        float py = fminf(fmaxf((gy + 1.f) * 0.5f * (float)(HF - 1), 0.f), (float)(HF - 1));
        int x0 = (int)floorf(px), y0 = (int)floorf(py);
        int x1 = min(x0 + 1, WF - 1), y1 = min(y0 + 1, HF - 1);
        float wx = px - (float)x0, wy = py - (float)y0;
        float2 v00 = G[y0 * WF + x0], v01 = G[y0 * WF + x1];
        float2 v10 = G[y1 * WF + x0], v11 = G[y1 * WF + x1];
        float dx = (v00.x * (1.f - wx) + v01.x * wx) * (1.f - wy)
                 + (v10.x * (1.f - wx) + v11.x * wx) * wy;
        float dy = (v00.y * (1.f - wx) + v01.y * wx) * (1.f - wy)
                 + (v10.y * (1.f - wx) + v11.y * wx) * wy;
        float len = sqrtf(dx * dx + dy * dy) + 0.01f;
        gx -= dx / len * stepx;
        gy -= dy / len * stepy;
    }

    // final image sample
    float px = fminf(fmaxf((gx + 1.f) * 0.5f * (float)(WF - 1), 0.f), (float)(WF - 1));
    float py = fminf(fmaxf((gy + 1.f) * 0.5f * (float)(HF - 1), 0.f), (float)(HF - 1));
    int x0 = (int)floorf(px), y0 = (int)floorf(py);
    int x1 = min(x0 + 1, WF - 1), y1 = min(y0 + 1, HF - 1);
    float wx = px - (float)x0, wy = py - (float)y0;
    float w00 = (1.f - wx) * (1.f - wy), w01 = wx * (1.f - wy);
    float w10 = (1.f - wx) * wy,         w11 = wx * wy;

    const float* base = img + (size_t)b * CC * HF * WF;
    float* obase = out + (size_t)b * CC * HF * WF;
    #pragma unroll
    for (int c = 0; c < CC; ++c) {
        const float* p = base + (size_t)c * HF * WF;
        float v = w00 * p[y0 * WF + x0] + w01 * p[y0 * WF + x1]
                + w10 * p[y1 * WF + x0] + w11 * p[y1 * WF + x1];
        obase[(size_t)c * HF * WF + (size_t)i * WF + j] = fminf(fmaxf(v, 0.f), 1.f);
    }
}

// ---------------------------------------------------------------------------
extern "C" void kernel_launch(void* const* d_in, const int* in_sizes, int n_in,
                              void* d_out, int out_size) {
    const float* img = (const float*)d_in[0];
    float* out = (float*)d_out;

    dim3 blk(128);
    dim3 grid_h((WH + 127) / 128, HH, BB);
    dim3 grid_f((WF + 127) / 128, HF, BB);

    k_luma_down <<<grid_h, blk>>>(img);
    k_edge_mag  <<<grid_h, blk>>>();
    k_blur_h    <<<grid_h, blk>>>();
    k_blur_v    <<<grid_h, blk>>>();
    k_grad_field<<<grid_h, blk>>>();
    k_upsample  <<<grid_f, blk>>>();
    k_warp      <<<grid_f, blk>>>(img, out);
}